// round 6
// baseline (speedup 1.0000x reference)
#include <cuda_runtime.h>
#include <cuda_fp16.h>

#define Nn    6144
#define EMB   256
#define HID   128
#define EPOS  98304
#define ENEG  24576
#define EPOT  262144
#define SIGMA 100.0f
#define TDEL  0.1f

#define TOT       (ENEG + EPOS + EPOT)   // 385024
#define NLOSS     (ENEG + EPOS)          // 122880
#define EDGE_BLKS (TOT / 32)             // 12032 (32 edges per block)
#define NEG_B     (ENEG / 32)            // 768
#define PN_B      (NLOSS / 32)           // 3840

// prep grid layout
#define B_EMB  (Nn * EMB / 1024)         // 1536 (4 floats per thread)
#define B_W    384
#define B_GATH (TOT / 256)               // 1504

// fp16 staging
__device__ __half hE[Nn * EMB];            // emb, row-major
__device__ __half hW1t[2][HID * EMB];      // n-major: [n*256 + k]
__device__ __half hW2t[2][HID * HID];      // n-major: [n*128 + k]
// latents: per node [link 0..127 | aa 128..255] = 512B
__device__ __half g_lat[Nn * 256];
// pre-gathered aa / fdiff values per edge (compact, coalesced for edge kernel)
__device__ float g_av[TOT];
__device__ float g_fd[NLOSS];
// spread loss accumulators (128B stride) + completion ticket
__device__ float g_loss[64 * 32];
__device__ unsigned g_done;

// ---------------------------------------------------------------------------
// prep: fp32->fp16 conversions, weight transpose, aa/fdiff edge gathers,
// loss zeroing. All independent -> one latency-bound kernel.
// ---------------------------------------------------------------------------
__global__ __launch_bounds__(256) void prep_kernel(
    const float* __restrict__ emb,
    const float* __restrict__ W1l, const float* __restrict__ W1a,
    const float* __restrict__ W2l, const float* __restrict__ W2a,
    const float* __restrict__ aa,  const float* __restrict__ fdiff,
    const int*   __restrict__ pos_e, const int* __restrict__ neg_e,
    const int*   __restrict__ pot_e)
{
    const int b = blockIdx.x, tid = threadIdx.x;
    if (b == 0 && tid < 64) g_loss[tid * 32] = 0.0f;
    if (b == 1 && tid == 0) g_done = 0;

    if (b < B_EMB) {
        // emb fp32 -> fp16, 4 elements per thread
        int idx = (b * 256 + tid) * 4;
        float4 f = *(const float4*)(emb + idx);
        __half2 h0 = __floats2half2_rn(f.x, f.y);
        __half2 h1 = __floats2half2_rn(f.z, f.w);
        uint2 st; st.x = *(unsigned*)&h0; st.y = *(unsigned*)&h1;
        *(uint2*)(hE + idx) = st;
    } else if (b < B_EMB + B_W) {
        // weight transposes (98304 elements)
        int widx = (b - B_EMB) * 256 + tid;
        if (widx < 2 * EMB * HID) {
            int br = widx >> 15;
            int t  = widx & 32767;
            int k  = t >> 7, n = t & 127;
            const float* W = br ? W1a : W1l;
            hW1t[br][n * EMB + k] = __float2half(W[k * HID + n]);
        } else {
            int t2 = widx - 2 * EMB * HID;
            int br = t2 >> 14;
            int t  = t2 & 16383;
            int k  = t >> 7, n = t & 127;
            const float* W = br ? W2a : W2l;
            hW2t[br][n * HID + k] = __float2half(W[k * HID + n]);
        }
    } else {
        // random gathers of aa / fdiff per edge -> compact arrays
        int e = (b - B_EMB - B_W) * 256 + tid;   // [0, TOT)
        int i, j;
        if (e < ENEG) {
            i = neg_e[e]; j = neg_e[ENEG + e];
        } else if (e < NLOSS) {
            int le = e - ENEG;
            i = pos_e[le]; j = pos_e[EPOS + le];
        } else {
            int le = e - NLOSS;
            i = pot_e[le]; j = pot_e[EPOT + le];
        }
        size_t off = (size_t)i * Nn + j;
        g_av[e] = __ldg(aa + off);
        if (e < NLOSS) g_fd[e] = __ldg(fdiff + off);
    }
}

// ---------------------------------------------------------------------------
// MLP via mma.sync.m16n8k16 (HMMA, fp16 in / fp32 accum).
// Block: 128 threads = 4 warps. Block tile: 64 rows x 128 cols.
// ---------------------------------------------------------------------------
__device__ __forceinline__ void mma16816(float* c, const unsigned* a,
                                         unsigned b0, unsigned b1) {
    asm volatile(
        "mma.sync.aligned.m16n8k16.row.col.f32.f16.f16.f32 "
        "{%0,%1,%2,%3}, {%4,%5,%6,%7}, {%8,%9}, {%0,%1,%2,%3};"
        : "+f"(c[0]), "+f"(c[1]), "+f"(c[2]), "+f"(c[3])
        : "r"(a[0]), "r"(a[1]), "r"(a[2]), "r"(a[3]), "r"(b0), "r"(b1));
}

#define SH_PITCH 136

__global__ __launch_bounds__(128) void mlp_kernel(
    const float* __restrict__ b1l, const float* __restrict__ b2l,
    const float* __restrict__ b1a, const float* __restrict__ b2a)
{
    __shared__ __half sH[64 * SH_PITCH];

    const int branch = blockIdx.y;
    const float* B1 = branch ? b1a : b1l;
    const float* B2 = branch ? b2a : b2l;
    const __half* W1 = hW1t[branch];
    const __half* W2 = hW2t[branch];

    const int tid  = threadIdx.x;
    const int w    = tid >> 5;
    const int lane = tid & 31;
    const int rg   = w & 1;
    const int cg   = w >> 1;
    const int r    = lane >> 2;
    const int c2   = (lane & 3) * 2;

    const int R0 = blockIdx.x * 64 + rg * 32;
    const int C0 = cg * 64;

    float acc[2][8][4];
    #pragma unroll
    for (int m = 0; m < 2; m++)
        #pragma unroll
        for (int n = 0; n < 8; n++)
            #pragma unroll
            for (int q = 0; q < 4; q++) acc[m][n][q] = 0.0f;

    // ---- stage 1: acc = emb @ W1 ----
    #pragma unroll 4
    for (int kt = 0; kt < EMB / 16; kt++) {
        const int k0 = kt * 16;
        unsigned a[2][4];
        #pragma unroll
        for (int m = 0; m < 2; m++) {
            const __half* Ab = hE + (size_t)(R0 + m * 16 + r) * EMB + k0 + c2;
            a[m][0] = *(const unsigned*)Ab;
            a[m][1] = *(const unsigned*)(Ab + 8 * EMB);
            a[m][2] = *(const unsigned*)(Ab + 8);
            a[m][3] = *(const unsigned*)(Ab + 8 * EMB + 8);
        }
        #pragma unroll
        for (int n = 0; n < 8; n++) {
            const __half* Bb = W1 + (size_t)(C0 + n * 8 + r) * EMB + k0 + c2;
            unsigned b0 = *(const unsigned*)Bb;
            unsigned b1v = *(const unsigned*)(Bb + 8);
            mma16816(acc[0][n], a[0], b0, b1v);
            mma16816(acc[1][n], a[1], b0, b1v);
        }
    }

    #pragma unroll
    for (int m = 0; m < 2; m++) {
        const int lr = rg * 32 + m * 16 + r;
        #pragma unroll
        for (int n = 0; n < 8; n++) {
            const int col = C0 + n * 8 + c2;
            float2 bv = *(const float2*)(B1 + col);
            __half2 h0 = __floats2half2_rn(fmaxf(acc[m][n][0] + bv.x, 0.0f),
                                           fmaxf(acc[m][n][1] + bv.y, 0.0f));
            __half2 h1 = __floats2half2_rn(fmaxf(acc[m][n][2] + bv.x, 0.0f),
                                           fmaxf(acc[m][n][3] + bv.y, 0.0f));
            *(unsigned*)(sH + lr * SH_PITCH + col)       = *(unsigned*)&h0;
            *(unsigned*)(sH + (lr + 8) * SH_PITCH + col) = *(unsigned*)&h1;
        }
    }
    __syncthreads();

    // ---- stage 2: acc = H @ W2 ----
    #pragma unroll
    for (int m = 0; m < 2; m++)
        #pragma unroll
        for (int n = 0; n < 8; n++)
            #pragma unroll
            for (int q = 0; q < 4; q++) acc[m][n][q] = 0.0f;

    #pragma unroll
    for (int kt = 0; kt < HID / 16; kt++) {
        const int k0 = kt * 16;
        unsigned a[2][4];
        #pragma unroll
        for (int m = 0; m < 2; m++) {
            const __half* Ab = sH + (rg * 32 + m * 16 + r) * SH_PITCH + k0 + c2;
            a[m][0] = *(const unsigned*)Ab;
            a[m][1] = *(const unsigned*)(Ab + 8 * SH_PITCH);
            a[m][2] = *(const unsigned*)(Ab + 8);
            a[m][3] = *(const unsigned*)(Ab + 8 * SH_PITCH + 8);
        }
        #pragma unroll
        for (int n = 0; n < 8; n++) {
            const __half* Bb = W2 + (size_t)(C0 + n * 8 + r) * HID + k0 + c2;
            unsigned b0 = *(const unsigned*)Bb;
            unsigned b1v = *(const unsigned*)(Bb + 8);
            mma16816(acc[0][n], a[0], b0, b1v);
            mma16816(acc[1][n], a[1], b0, b1v);
        }
    }

    #pragma unroll
    for (int m = 0; m < 2; m++) {
        const int row0 = R0 + m * 16 + r;
        #pragma unroll
        for (int n = 0; n < 8; n++) {
            const int col = C0 + n * 8 + c2;
            float2 bv = *(const float2*)(B2 + col);
            __half2 h0 = __floats2half2_rn(acc[m][n][0] + bv.x, acc[m][n][1] + bv.y);
            __half2 h1 = __floats2half2_rn(acc[m][n][2] + bv.x, acc[m][n][3] + bv.y);
            *(unsigned*)(g_lat + (size_t)row0 * 256 + branch * 128 + col)       = *(unsigned*)&h0;
            *(unsigned*)(g_lat + (size_t)(row0 + 8) * 256 + branch * 128 + col) = *(unsigned*)&h1;
        }
    }
}

// ---------------------------------------------------------------------------
// Edge kernel: FOUR edges per warp (8-lane groups), 32 edges per block.
// Group lanes s=0..3 cover the link half, s=4..7 the aa half (2 uint4 each
// per node row -> fully coalesced 512B). Reduce: shfl 1,2 then swap via 4.
// aa/fdiff come pre-gathered (compact arrays). Last block folds finalize.
// ---------------------------------------------------------------------------
__device__ __forceinline__ float fsigmoid(float x) {
    return 1.0f / (1.0f + __expf(-x));
}

__device__ __forceinline__ float dot16h(uint4 u, uint4 v) {
    float d = 0.0f;
    float2 a, c;
    a = __half22float2(*(const __half2*)&u.x); c = __half22float2(*(const __half2*)&v.x);
    d += a.x * c.x + a.y * c.y;
    a = __half22float2(*(const __half2*)&u.y); c = __half22float2(*(const __half2*)&v.y);
    d += a.x * c.x + a.y * c.y;
    a = __half22float2(*(const __half2*)&u.z); c = __half22float2(*(const __half2*)&v.z);
    d += a.x * c.x + a.y * c.y;
    a = __half22float2(*(const __half2*)&u.w); c = __half22float2(*(const __half2*)&v.w);
    d += a.x * c.x + a.y * c.y;
    return d;
}

__global__ __launch_bounds__(256) void edge_kernel(
    const int*   __restrict__ pos_e,
    const int*   __restrict__ neg_e,
    const int*   __restrict__ pot_e,
    const float* __restrict__ emb_w,
    const float* __restrict__ struct_w,
    float* __restrict__ out)
{
    const int b    = blockIdx.x;
    const int tid  = threadIdx.x;
    const int warp = tid >> 5;
    const int lane = tid & 31;
    const int g    = lane >> 3;       // edge within warp (0..3)
    const int s    = lane & 7;        // sub-lane within 8-lane group
    const int e    = b * 32 + warp * 4 + g;

    int i, j;
    if (b < NEG_B) {
        i = neg_e[e]; j = neg_e[ENEG + e];
    } else if (b < PN_B) {
        int le = e - ENEG;
        i = pos_e[le]; j = pos_e[EPOS + le];
    } else {
        int le = e - NLOSS;
        i = pot_e[le]; j = pot_e[EPOT + le];
    }

    // pre-gathered scalars (L2-resident, coalesced across leaders)
    float aval = 0.0f, fdv = 0.0f;
    if (s == 0) {
        aval = g_av[e];
        if (b < PN_B) fdv = g_fd[e];
    }

    // each lane: 32B (2 uint4) of its half from each node row
    const uint4* Ri = (const uint4*)(g_lat + (size_t)i * 256);
    const uint4* Rj = (const uint4*)(g_lat + (size_t)j * 256);
    const int base = s * 2;   // link half for s<4 (idx 0..7), aa half s>=4 (8..15)
    uint4 u0 = Ri[2 * base],     v0 = Rj[2 * base];
    uint4 u1 = Ri[2 * base + 1], v1 = Rj[2 * base + 1];
    uint4 u2 = Ri[2 * base + 2], v2 = Rj[2 * base + 2];
    uint4 u3 = Ri[2 * base + 3], v3 = Rj[2 * base + 3];

    float d = dot16h(u0, v0) + dot16h(u1, v1) + dot16h(u2, v2) + dot16h(u3, v3);

    // reduce within 4-lane sub-group, then swap halves
    d += __shfl_xor_sync(0xffffffffu, d, 1);
    d += __shfl_xor_sync(0xffffffffu, d, 2);
    float dother = __shfl_xor_sync(0xffffffffu, d, 4);   // leader gets aa-dot

    if (s == 0) {
        float ew = emb_w[0], sw = struct_w[0];
        float lc = fsigmoid(d);
        float ac = fsigmoid(dother * aval);
        float vv = fsigmoid(ew * lc + sw * ac);
        if (b >= PN_B) {
            out[1 + e - NLOSS] = (vv < TDEL) ? 0.0f : vv;
        } else {
            float fd = fdv * (1.0f / SIGMA);
            float q = fd * fd;
            float contrib;
            if (b >= NEG_B) {                // positive edge
                float e1 = vv - 1.0f;
                contrib = __expf(-q) * e1 * e1;
            } else {                          // negative edge
                contrib = __expf(q) * vv * vv;
            }
            atomicAdd(&g_loss[(e & 63) * 32], contrib);
            __threadfence();
        }
    }

    // ---- folded finalize: last block to retire does the reduction ----
    __syncthreads();
    if (tid == 0) {
        unsigned t = atomicAdd(&g_done, 1u);
        if (t == (unsigned)(EDGE_BLKS - 1)) {
            __threadfence();
            float sum = 0.0f;
            #pragma unroll
            for (int q = 0; q < 64; q++) sum += g_loss[q * 32];
            out[0] = sum * ((float)Nn / (float)NLOSS);
            g_done = 0;
        }
    }
}

// ---------------------------------------------------------------------------
extern "C" void kernel_launch(void* const* d_in, const int* in_sizes, int n_in,
                              void* d_out, int out_size)
{
    const float* emb   = (const float*)d_in[0];
    const float* aa    = (const float*)d_in[1];
    const float* fdiff = (const float*)d_in[2];
    const float* W1l   = (const float*)d_in[3];
    const float* b1l   = (const float*)d_in[4];
    const float* W2l   = (const float*)d_in[5];
    const float* b2l   = (const float*)d_in[6];
    const float* W1a   = (const float*)d_in[7];
    const float* b1a   = (const float*)d_in[8];
    const float* W2a   = (const float*)d_in[9];
    const float* b2a   = (const float*)d_in[10];
    const float* emw   = (const float*)d_in[11];
    const float* stw   = (const float*)d_in[12];
    const int*   pose  = (const int*)d_in[13];
    const int*   nege  = (const int*)d_in[14];
    const int*   pote  = (const int*)d_in[15];
    float* out = (float*)d_out;

    prep_kernel<<<B_EMB + B_W + B_GATH, 256>>>(emb, W1l, W1a, W2l, W2a,
                                               aa, fdiff, pose, nege, pote);

    dim3 mgrid(Nn / 64, 2);
    mlp_kernel<<<mgrid, 128>>>(b1l, b2l, b1a, b2a);

    edge_kernel<<<EDGE_BLKS, 256>>>(pose, nege, pote, emw, stw, out);
}

// round 8
// speedup vs baseline: 1.3655x; 1.3655x over previous
#include <cuda_runtime.h>
#include <cuda_fp16.h>

#define Nn    6144
#define EMB   256
#define HID   128
#define EPOS  98304
#define ENEG  24576
#define EPOT  262144
#define SIGMA 100.0f
#define TDEL  0.1f

#define TOT       (ENEG + EPOS + EPOT)   // 385024
#define NLOSS     (ENEG + EPOS)          // 122880
#define EDGE_BLKS (TOT / 32)             // 12032 (32 edges per block)
#define NEG_B     (ENEG / 32)            // 768
#define PN_B      (NLOSS / 32)           // 3840

// prep grid layout
#define B_EMB  (Nn * EMB / 1024)         // 1536 (4 floats per thread)
#define B_W    384

// fp16 staging
__device__ __half hE[Nn * EMB];            // emb, row-major
__device__ __half hW1t[2][HID * EMB];      // n-major: [n*256 + k]
__device__ __half hW2t[2][HID * HID];      // n-major: [n*128 + k]
// latents: per node [link 0..127 | aa 128..255] = 512B
__device__ __half g_lat[Nn * 256];
// spread loss accumulators (128B stride) + completion ticket
__device__ float g_loss[64 * 32];
__device__ unsigned g_done;

// ---------------------------------------------------------------------------
// prep: fp32->fp16 conversions + weight transpose + loss zeroing
// ---------------------------------------------------------------------------
__global__ __launch_bounds__(256) void prep_kernel(
    const float* __restrict__ emb,
    const float* __restrict__ W1l, const float* __restrict__ W1a,
    const float* __restrict__ W2l, const float* __restrict__ W2a)
{
    const int b = blockIdx.x, tid = threadIdx.x;
    if (b == 0 && tid < 64) g_loss[tid * 32] = 0.0f;
    if (b == 1 && tid == 0) g_done = 0;

    if (b < B_EMB) {
        // emb fp32 -> fp16, 4 elements per thread
        int idx = (b * 256 + tid) * 4;
        float4 f = *(const float4*)(emb + idx);
        __half2 h0 = __floats2half2_rn(f.x, f.y);
        __half2 h1 = __floats2half2_rn(f.z, f.w);
        uint2 st; st.x = *(unsigned*)&h0; st.y = *(unsigned*)&h1;
        *(uint2*)(hE + idx) = st;
    } else {
        // weight transposes (98304 elements)
        int widx = (b - B_EMB) * 256 + tid;
        if (widx < 2 * EMB * HID) {
            int br = widx >> 15;
            int t  = widx & 32767;
            int k  = t >> 7, n = t & 127;
            const float* W = br ? W1a : W1l;
            hW1t[br][n * EMB + k] = __float2half(W[k * HID + n]);
        } else {
            int t2 = widx - 2 * EMB * HID;
            int br = t2 >> 14;
            int t  = t2 & 16383;
            int k  = t >> 7, n = t & 127;
            const float* W = br ? W2a : W2l;
            hW2t[br][n * HID + k] = __float2half(W[k * HID + n]);
        }
    }
}

// ---------------------------------------------------------------------------
// MLP via mma.sync.m16n8k16 (HMMA, fp16 in / fp32 accum).
// Block: 128 threads = 4 warps. Block tile: 64 rows x 128 cols.
// ---------------------------------------------------------------------------
__device__ __forceinline__ void mma16816(float* c, const unsigned* a,
                                         unsigned b0, unsigned b1) {
    asm volatile(
        "mma.sync.aligned.m16n8k16.row.col.f32.f16.f16.f32 "
        "{%0,%1,%2,%3}, {%4,%5,%6,%7}, {%8,%9}, {%0,%1,%2,%3};"
        : "+f"(c[0]), "+f"(c[1]), "+f"(c[2]), "+f"(c[3])
        : "r"(a[0]), "r"(a[1]), "r"(a[2]), "r"(a[3]), "r"(b0), "r"(b1));
}

#define SH_PITCH 136

__global__ __launch_bounds__(128) void mlp_kernel(
    const float* __restrict__ b1l, const float* __restrict__ b2l,
    const float* __restrict__ b1a, const float* __restrict__ b2a)
{
    __shared__ __half sH[64 * SH_PITCH];

    const int branch = blockIdx.y;
    const float* B1 = branch ? b1a : b1l;
    const float* B2 = branch ? b2a : b2l;
    const __half* W1 = hW1t[branch];
    const __half* W2 = hW2t[branch];

    const int tid  = threadIdx.x;
    const int w    = tid >> 5;
    const int lane = tid & 31;
    const int rg   = w & 1;
    const int cg   = w >> 1;
    const int r    = lane >> 2;
    const int c2   = (lane & 3) * 2;

    const int R0 = blockIdx.x * 64 + rg * 32;
    const int C0 = cg * 64;

    float acc[2][8][4];
    #pragma unroll
    for (int m = 0; m < 2; m++)
        #pragma unroll
        for (int n = 0; n < 8; n++)
            #pragma unroll
            for (int q = 0; q < 4; q++) acc[m][n][q] = 0.0f;

    // ---- stage 1: acc = emb @ W1 ----
    #pragma unroll 4
    for (int kt = 0; kt < EMB / 16; kt++) {
        const int k0 = kt * 16;
        unsigned a[2][4];
        #pragma unroll
        for (int m = 0; m < 2; m++) {
            const __half* Ab = hE + (size_t)(R0 + m * 16 + r) * EMB + k0 + c2;
            a[m][0] = *(const unsigned*)Ab;
            a[m][1] = *(const unsigned*)(Ab + 8 * EMB);
            a[m][2] = *(const unsigned*)(Ab + 8);
            a[m][3] = *(const unsigned*)(Ab + 8 * EMB + 8);
        }
        #pragma unroll
        for (int n = 0; n < 8; n++) {
            const __half* Bb = W1 + (size_t)(C0 + n * 8 + r) * EMB + k0 + c2;
            unsigned b0 = *(const unsigned*)Bb;
            unsigned b1v = *(const unsigned*)(Bb + 8);
            mma16816(acc[0][n], a[0], b0, b1v);
            mma16816(acc[1][n], a[1], b0, b1v);
        }
    }

    #pragma unroll
    for (int m = 0; m < 2; m++) {
        const int lr = rg * 32 + m * 16 + r;
        #pragma unroll
        for (int n = 0; n < 8; n++) {
            const int col = C0 + n * 8 + c2;
            float2 bv = *(const float2*)(B1 + col);
            __half2 h0 = __floats2half2_rn(fmaxf(acc[m][n][0] + bv.x, 0.0f),
                                           fmaxf(acc[m][n][1] + bv.y, 0.0f));
            __half2 h1 = __floats2half2_rn(fmaxf(acc[m][n][2] + bv.x, 0.0f),
                                           fmaxf(acc[m][n][3] + bv.y, 0.0f));
            *(unsigned*)(sH + lr * SH_PITCH + col)       = *(unsigned*)&h0;
            *(unsigned*)(sH + (lr + 8) * SH_PITCH + col) = *(unsigned*)&h1;
        }
    }
    __syncthreads();

    // ---- stage 2: acc = H @ W2 ----
    #pragma unroll
    for (int m = 0; m < 2; m++)
        #pragma unroll
        for (int n = 0; n < 8; n++)
            #pragma unroll
            for (int q = 0; q < 4; q++) acc[m][n][q] = 0.0f;

    #pragma unroll
    for (int kt = 0; kt < HID / 16; kt++) {
        const int k0 = kt * 16;
        unsigned a[2][4];
        #pragma unroll
        for (int m = 0; m < 2; m++) {
            const __half* Ab = sH + (rg * 32 + m * 16 + r) * SH_PITCH + k0 + c2;
            a[m][0] = *(const unsigned*)Ab;
            a[m][1] = *(const unsigned*)(Ab + 8 * SH_PITCH);
            a[m][2] = *(const unsigned*)(Ab + 8);
            a[m][3] = *(const unsigned*)(Ab + 8 * SH_PITCH + 8);
        }
        #pragma unroll
        for (int n = 0; n < 8; n++) {
            const __half* Bb = W2 + (size_t)(C0 + n * 8 + r) * HID + k0 + c2;
            unsigned b0 = *(const unsigned*)Bb;
            unsigned b1v = *(const unsigned*)(Bb + 8);
            mma16816(acc[0][n], a[0], b0, b1v);
            mma16816(acc[1][n], a[1], b0, b1v);
        }
    }

    #pragma unroll
    for (int m = 0; m < 2; m++) {
        const int row0 = R0 + m * 16 + r;
        #pragma unroll
        for (int n = 0; n < 8; n++) {
            const int col = C0 + n * 8 + c2;
            float2 bv = *(const float2*)(B2 + col);
            __half2 h0 = __floats2half2_rn(acc[m][n][0] + bv.x, acc[m][n][1] + bv.y);
            __half2 h1 = __floats2half2_rn(acc[m][n][2] + bv.x, acc[m][n][3] + bv.y);
            *(unsigned*)(g_lat + (size_t)row0 * 256 + branch * 128 + col)       = *(unsigned*)&h0;
            *(unsigned*)(g_lat + (size_t)(row0 + 8) * 256 + branch * 128 + col) = *(unsigned*)&h1;
        }
    }
}

// ---------------------------------------------------------------------------
// Edge kernel: FOUR edges per warp, INTERLEAVED lane layout.
// 8-lane group; lane s loads Ri[s], Ri[s+8] (link) and Ri[s+16], Ri[s+24]
// (aa) -> every LDG.128 across the group covers one full 128B line.
// Two independent 3-level shfl reductions; leader holds BOTH dots.
// aa/fdiff gathered by leader BEFORE latent loads (latency overlap).
// Last block folds the finalize reduction (ticket pattern).
// ---------------------------------------------------------------------------
__device__ __forceinline__ float fsigmoid(float x) {
    return 1.0f / (1.0f + __expf(-x));
}

__device__ __forceinline__ float dot16h(uint4 u, uint4 v) {
    float d = 0.0f;
    float2 a, c;
    a = __half22float2(*(const __half2*)&u.x); c = __half22float2(*(const __half2*)&v.x);
    d += a.x * c.x + a.y * c.y;
    a = __half22float2(*(const __half2*)&u.y); c = __half22float2(*(const __half2*)&v.y);
    d += a.x * c.x + a.y * c.y;
    a = __half22float2(*(const __half2*)&u.z); c = __half22float2(*(const __half2*)&v.z);
    d += a.x * c.x + a.y * c.y;
    a = __half22float2(*(const __half2*)&u.w); c = __half22float2(*(const __half2*)&v.w);
    d += a.x * c.x + a.y * c.y;
    return d;
}

__global__ __launch_bounds__(256) void edge_kernel(
    const float* __restrict__ aa,
    const float* __restrict__ fdiff,
    const int*   __restrict__ pos_e,
    const int*   __restrict__ neg_e,
    const int*   __restrict__ pot_e,
    const float* __restrict__ emb_w,
    const float* __restrict__ struct_w,
    float* __restrict__ out)
{
    const int b    = blockIdx.x;
    const int tid  = threadIdx.x;
    const int warp = tid >> 5;
    const int lane = tid & 31;
    const int g    = lane >> 3;       // edge within warp (0..3)
    const int s    = lane & 7;        // sub-lane within 8-lane group
    const int e    = b * 32 + warp * 4 + g;

    int i, j;
    if (b < NEG_B) {
        i = neg_e[e]; j = neg_e[ENEG + e];
    } else if (b < PN_B) {
        int le = e - ENEG;
        i = pos_e[le]; j = pos_e[EPOS + le];
    } else {
        int le = e - NLOSS;
        i = pot_e[le]; j = pot_e[EPOT + le];
    }

    // early DRAM gathers by the leader lane — overlap with the dot work below
    float aval = 0.0f, fdv = 0.0f;
    if (s == 0) {
        aval = __ldg(aa + (size_t)i * Nn + j);
        if (b < PN_B) fdv = __ldg(fdiff + (size_t)i * Nn + j);
    }

    // interleaved loads: idx 0..15 = link half, 16..31 = aa half
    const uint4* Ri = (const uint4*)(g_lat + (size_t)i * 256);
    const uint4* Rj = (const uint4*)(g_lat + (size_t)j * 256);
    uint4 u0 = Ri[s],      v0 = Rj[s];
    uint4 u1 = Ri[s + 8],  v1 = Rj[s + 8];
    uint4 u2 = Ri[s + 16], v2 = Rj[s + 16];
    uint4 u3 = Ri[s + 24], v3 = Rj[s + 24];

    float d1 = dot16h(u0, v0) + dot16h(u1, v1);   // link dot partial
    float d2 = dot16h(u2, v2) + dot16h(u3, v3);   // aa dot partial

    // two independent 3-level reductions within the 8-lane group
    d1 += __shfl_xor_sync(0xffffffffu, d1, 1);
    d2 += __shfl_xor_sync(0xffffffffu, d2, 1);
    d1 += __shfl_xor_sync(0xffffffffu, d1, 2);
    d2 += __shfl_xor_sync(0xffffffffu, d2, 2);
    d1 += __shfl_xor_sync(0xffffffffu, d1, 4);
    d2 += __shfl_xor_sync(0xffffffffu, d2, 4);

    if (s == 0) {
        float ew = emb_w[0], sw = struct_w[0];
        float lc = fsigmoid(d1);
        float ac = fsigmoid(d2 * aval);
        float vv = fsigmoid(ew * lc + sw * ac);
        if (b >= PN_B) {
            out[1 + e - NLOSS] = (vv < TDEL) ? 0.0f : vv;
        } else {
            float fd = fdv * (1.0f / SIGMA);
            float q = fd * fd;
            float contrib;
            if (b >= NEG_B) {                // positive edge
                float e1 = vv - 1.0f;
                contrib = __expf(-q) * e1 * e1;
            } else {                          // negative edge
                contrib = __expf(q) * vv * vv;
            }
            atomicAdd(&g_loss[(e & 63) * 32], contrib);
            __threadfence();
        }
    }

    // ---- folded finalize: last block to retire does the reduction ----
    __syncthreads();
    if (tid == 0) {
        unsigned t = atomicAdd(&g_done, 1u);
        if (t == (unsigned)(EDGE_BLKS - 1)) {
            __threadfence();
            float sum = 0.0f;
            #pragma unroll
            for (int q = 0; q < 64; q++) sum += g_loss[q * 32];
            out[0] = sum * ((float)Nn / (float)NLOSS);
            g_done = 0;
        }
    }
}

// ---------------------------------------------------------------------------
extern "C" void kernel_launch(void* const* d_in, const int* in_sizes, int n_in,
                              void* d_out, int out_size)
{
    const float* emb   = (const float*)d_in[0];
    const float* aa    = (const float*)d_in[1];
    const float* fdiff = (const float*)d_in[2];
    const float* W1l   = (const float*)d_in[3];
    const float* b1l   = (const float*)d_in[4];
    const float* W2l   = (const float*)d_in[5];
    const float* b2l   = (const float*)d_in[6];
    const float* W1a   = (const float*)d_in[7];
    const float* b1a   = (const float*)d_in[8];
    const float* W2a   = (const float*)d_in[9];
    const float* b2a   = (const float*)d_in[10];
    const float* emw   = (const float*)d_in[11];
    const float* stw   = (const float*)d_in[12];
    const int*   pose  = (const int*)d_in[13];
    const int*   nege  = (const int*)d_in[14];
    const int*   pote  = (const int*)d_in[15];
    float* out = (float*)d_out;

    prep_kernel<<<B_EMB + B_W, 256>>>(emb, W1l, W1a, W2l, W2a);

    dim3 mgrid(Nn / 64, 2);
    mlp_kernel<<<mgrid, 128>>>(b1l, b2l, b1a, b2a);

    edge_kernel<<<EDGE_BLKS, 256>>>(aa, fdiff, pose, nege, pote, emw, stw, out);
}

// round 9
// speedup vs baseline: 1.4036x; 1.0279x over previous
#include <cuda_runtime.h>
#include <cuda_fp16.h>

#define Nn    6144
#define EMB   256
#define HID   128
#define EPOS  98304
#define ENEG  24576
#define EPOT  262144
#define SIGMA 100.0f
#define TDEL  0.1f

#define TOT       (ENEG + EPOS + EPOT)   // 385024
#define NLOSS     (ENEG + EPOS)          // 122880
#define EDGE_BLKS (TOT / 32)             // 12032 (32 edges per block)
#define NEG_B     (ENEG / 32)            // 768
#define PN_B      (NLOSS / 32)           // 3840 (loss blocks)

// fp16 staging (weights only; emb converted in-flight by mlp)
__device__ __half hW1t[2][HID * EMB];      // n-major: [n*256 + k]
__device__ __half hW2t[2][HID * HID];      // n-major: [n*128 + k]
// latents: per node [link 0..127 | aa 128..255] = 512B
__device__ __half g_lat[Nn * 256];
// spread loss accumulators (128B stride) + completion ticket
__device__ float g_loss[64 * 32];
__device__ unsigned g_done;

// ---------------------------------------------------------------------------
// prep: weight transpose fp32->fp16 + loss zeroing. 384 blocks.
// ---------------------------------------------------------------------------
__global__ __launch_bounds__(256) void prep_kernel(
    const float* __restrict__ W1l, const float* __restrict__ W1a,
    const float* __restrict__ W2l, const float* __restrict__ W2a)
{
    const int b = blockIdx.x, tid = threadIdx.x;
    if (b == 0 && tid < 64) g_loss[tid * 32] = 0.0f;
    if (b == 1 && tid == 0) g_done = 0;

    int widx = b * 256 + tid;                 // [0, 98304)
    if (widx < 2 * EMB * HID) {               // W1 transposes
        int br = widx >> 15;
        int t  = widx & 32767;
        int k  = t >> 7, n = t & 127;
        const float* W = br ? W1a : W1l;
        hW1t[br][n * EMB + k] = __float2half(W[k * HID + n]);
    } else {
        int t2 = widx - 2 * EMB * HID;
        int br = t2 >> 14;
        int t  = t2 & 16383;
        int k  = t >> 7, n = t & 127;
        const float* W = br ? W2a : W2l;
        hW2t[br][n * HID + k] = __float2half(W[k * HID + n]);
    }
}

// ---------------------------------------------------------------------------
// MLP via mma.sync.m16n8k16 (HMMA, fp16 in / fp32 accum).
// Block: 128 threads = 4 warps. Block tile: 64 rows x 128 cols.
// A fragments loaded from fp32 emb and converted in registers.
// ---------------------------------------------------------------------------
__device__ __forceinline__ void mma16816(float* c, const unsigned* a,
                                         unsigned b0, unsigned b1) {
    asm volatile(
        "mma.sync.aligned.m16n8k16.row.col.f32.f16.f16.f32 "
        "{%0,%1,%2,%3}, {%4,%5,%6,%7}, {%8,%9}, {%0,%1,%2,%3};"
        : "+f"(c[0]), "+f"(c[1]), "+f"(c[2]), "+f"(c[3])
        : "r"(a[0]), "r"(a[1]), "r"(a[2]), "r"(a[3]), "r"(b0), "r"(b1));
}

__device__ __forceinline__ unsigned cvt2(float2 f) {
    __half2 h = __floats2half2_rn(f.x, f.y);
    return *(unsigned*)&h;
}

#define SH_PITCH 136

__global__ __launch_bounds__(128) void mlp_kernel(
    const float* __restrict__ emb,
    const float* __restrict__ b1l, const float* __restrict__ b2l,
    const float* __restrict__ b1a, const float* __restrict__ b2a)
{
    __shared__ __half sH[64 * SH_PITCH];

    const int branch = blockIdx.y;
    const float* B1 = branch ? b1a : b1l;
    const float* B2 = branch ? b2a : b2l;
    const __half* W1 = hW1t[branch];
    const __half* W2 = hW2t[branch];

    const int tid  = threadIdx.x;
    const int w    = tid >> 5;
    const int lane = tid & 31;
    const int rg   = w & 1;
    const int cg   = w >> 1;
    const int r    = lane >> 2;
    const int c2   = (lane & 3) * 2;

    const int R0 = blockIdx.x * 64 + rg * 32;
    const int C0 = cg * 64;

    float acc[2][8][4];
    #pragma unroll
    for (int m = 0; m < 2; m++)
        #pragma unroll
        for (int n = 0; n < 8; n++)
            #pragma unroll
            for (int q = 0; q < 4; q++) acc[m][n][q] = 0.0f;

    // ---- stage 1: acc = emb @ W1 (A from fp32, converted in-flight) ----
    #pragma unroll 4
    for (int kt = 0; kt < EMB / 16; kt++) {
        const int k0 = kt * 16;
        unsigned a[2][4];
        #pragma unroll
        for (int m = 0; m < 2; m++) {
            const float* Af = emb + (size_t)(R0 + m * 16 + r) * EMB + k0 + c2;
            a[m][0] = cvt2(*(const float2*)Af);
            a[m][1] = cvt2(*(const float2*)(Af + 8 * EMB));
            a[m][2] = cvt2(*(const float2*)(Af + 8));
            a[m][3] = cvt2(*(const float2*)(Af + 8 * EMB + 8));
        }
        #pragma unroll
        for (int n = 0; n < 8; n++) {
            const __half* Bb = W1 + (size_t)(C0 + n * 8 + r) * EMB + k0 + c2;
            unsigned b0 = *(const unsigned*)Bb;
            unsigned b1v = *(const unsigned*)(Bb + 8);
            mma16816(acc[0][n], a[0], b0, b1v);
            mma16816(acc[1][n], a[1], b0, b1v);
        }
    }

    #pragma unroll
    for (int m = 0; m < 2; m++) {
        const int lr = rg * 32 + m * 16 + r;
        #pragma unroll
        for (int n = 0; n < 8; n++) {
            const int col = C0 + n * 8 + c2;
            float2 bv = *(const float2*)(B1 + col);
            __half2 h0 = __floats2half2_rn(fmaxf(acc[m][n][0] + bv.x, 0.0f),
                                           fmaxf(acc[m][n][1] + bv.y, 0.0f));
            __half2 h1 = __floats2half2_rn(fmaxf(acc[m][n][2] + bv.x, 0.0f),
                                           fmaxf(acc[m][n][3] + bv.y, 0.0f));
            *(unsigned*)(sH + lr * SH_PITCH + col)       = *(unsigned*)&h0;
            *(unsigned*)(sH + (lr + 8) * SH_PITCH + col) = *(unsigned*)&h1;
        }
    }
    __syncthreads();

    // ---- stage 2: acc = H @ W2 ----
    #pragma unroll
    for (int m = 0; m < 2; m++)
        #pragma unroll
        for (int n = 0; n < 8; n++)
            #pragma unroll
            for (int q = 0; q < 4; q++) acc[m][n][q] = 0.0f;

    #pragma unroll
    for (int kt = 0; kt < HID / 16; kt++) {
        const int k0 = kt * 16;
        unsigned a[2][4];
        #pragma unroll
        for (int m = 0; m < 2; m++) {
            const __half* Ab = sH + (rg * 32 + m * 16 + r) * SH_PITCH + k0 + c2;
            a[m][0] = *(const unsigned*)Ab;
            a[m][1] = *(const unsigned*)(Ab + 8 * SH_PITCH);
            a[m][2] = *(const unsigned*)(Ab + 8);
            a[m][3] = *(const unsigned*)(Ab + 8 * SH_PITCH + 8);
        }
        #pragma unroll
        for (int n = 0; n < 8; n++) {
            const __half* Bb = W2 + (size_t)(C0 + n * 8 + r) * HID + k0 + c2;
            unsigned b0 = *(const unsigned*)Bb;
            unsigned b1v = *(const unsigned*)(Bb + 8);
            mma16816(acc[0][n], a[0], b0, b1v);
            mma16816(acc[1][n], a[1], b0, b1v);
        }
    }

    #pragma unroll
    for (int m = 0; m < 2; m++) {
        const int row0 = R0 + m * 16 + r;
        #pragma unroll
        for (int n = 0; n < 8; n++) {
            const int col = C0 + n * 8 + c2;
            float2 bv = *(const float2*)(B2 + col);
            __half2 h0 = __floats2half2_rn(acc[m][n][0] + bv.x, acc[m][n][1] + bv.y);
            __half2 h1 = __floats2half2_rn(acc[m][n][2] + bv.x, acc[m][n][3] + bv.y);
            *(unsigned*)(g_lat + (size_t)row0 * 256 + branch * 128 + col)       = *(unsigned*)&h0;
            *(unsigned*)(g_lat + (size_t)(row0 + 8) * 256 + branch * 128 + col) = *(unsigned*)&h1;
        }
    }
}

// ---------------------------------------------------------------------------
// Edge kernel: FOUR edges per warp, interleaved lane layout (R8 proven).
// Loss blocks [0, PN_B) run the finalize ticket; pot blocks skip it.
// ---------------------------------------------------------------------------
__device__ __forceinline__ float fsigmoid(float x) {
    return 1.0f / (1.0f + __expf(-x));
}

__device__ __forceinline__ float dot16h(uint4 u, uint4 v) {
    float d = 0.0f;
    float2 a, c;
    a = __half22float2(*(const __half2*)&u.x); c = __half22float2(*(const __half2*)&v.x);
    d += a.x * c.x + a.y * c.y;
    a = __half22float2(*(const __half2*)&u.y); c = __half22float2(*(const __half2*)&v.y);
    d += a.x * c.x + a.y * c.y;
    a = __half22float2(*(const __half2*)&u.z); c = __half22float2(*(const __half2*)&v.z);
    d += a.x * c.x + a.y * c.y;
    a = __half22float2(*(const __half2*)&u.w); c = __half22float2(*(const __half2*)&v.w);
    d += a.x * c.x + a.y * c.y;
    return d;
}

__global__ __launch_bounds__(256) void edge_kernel(
    const float* __restrict__ aa,
    const float* __restrict__ fdiff,
    const int*   __restrict__ pos_e,
    const int*   __restrict__ neg_e,
    const int*   __restrict__ pot_e,
    const float* __restrict__ emb_w,
    const float* __restrict__ struct_w,
    float* __restrict__ out)
{
    const int b    = blockIdx.x;
    const int tid  = threadIdx.x;
    const int warp = tid >> 5;
    const int lane = tid & 31;
    const int g    = lane >> 3;       // edge within warp (0..3)
    const int s    = lane & 7;        // sub-lane within 8-lane group
    const int e    = b * 32 + warp * 4 + g;

    int i, j;
    if (b < NEG_B) {
        i = neg_e[e]; j = neg_e[ENEG + e];
    } else if (b < PN_B) {
        int le = e - ENEG;
        i = pos_e[le]; j = pos_e[EPOS + le];
    } else {
        int le = e - NLOSS;
        i = pot_e[le]; j = pot_e[EPOT + le];
    }

    // early DRAM gathers by the leader lane — overlap with the dot work below
    float aval = 0.0f, fdv = 0.0f;
    if (s == 0) {
        aval = __ldg(aa + (size_t)i * Nn + j);
        if (b < PN_B) fdv = __ldg(fdiff + (size_t)i * Nn + j);
    }

    // interleaved loads: idx 0..15 = link half, 16..31 = aa half
    const uint4* Ri = (const uint4*)(g_lat + (size_t)i * 256);
    const uint4* Rj = (const uint4*)(g_lat + (size_t)j * 256);
    uint4 u0 = Ri[s],      v0 = Rj[s];
    uint4 u1 = Ri[s + 8],  v1 = Rj[s + 8];
    uint4 u2 = Ri[s + 16], v2 = Rj[s + 16];
    uint4 u3 = Ri[s + 24], v3 = Rj[s + 24];

    float d1 = dot16h(u0, v0) + dot16h(u1, v1);   // link dot partial
    float d2 = dot16h(u2, v2) + dot16h(u3, v3);   // aa dot partial

    // two independent 3-level reductions within the 8-lane group
    d1 += __shfl_xor_sync(0xffffffffu, d1, 1);
    d2 += __shfl_xor_sync(0xffffffffu, d2, 1);
    d1 += __shfl_xor_sync(0xffffffffu, d1, 2);
    d2 += __shfl_xor_sync(0xffffffffu, d2, 2);
    d1 += __shfl_xor_sync(0xffffffffu, d1, 4);
    d2 += __shfl_xor_sync(0xffffffffu, d2, 4);

    if (s == 0) {
        float ew = emb_w[0], sw = struct_w[0];
        float lc = fsigmoid(d1);
        float ac = fsigmoid(d2 * aval);
        float vv = fsigmoid(ew * lc + sw * ac);
        if (b >= PN_B) {
            out[1 + e - NLOSS] = (vv < TDEL) ? 0.0f : vv;
        } else {
            float fd = fdv * (1.0f / SIGMA);
            float q = fd * fd;
            float contrib;
            if (b >= NEG_B) {                // positive edge
                float e1 = vv - 1.0f;
                contrib = __expf(-q) * e1 * e1;
            } else {                          // negative edge
                contrib = __expf(q) * vv * vv;
            }
            atomicAdd(&g_loss[(e & 63) * 32], contrib);
            __threadfence();                  // REDG device-visible before ticket
        }
    }

    // ---- folded finalize: only LOSS blocks participate in the ticket ----
    if (b < PN_B) {
        __syncthreads();
        if (tid == 0) {
            unsigned t = atomicAdd(&g_done, 1u);
            if (t == (unsigned)(PN_B - 1)) {
                __threadfence();
                float sum = 0.0f;
                #pragma unroll
                for (int q = 0; q < 64; q++) sum += g_loss[q * 32];
                out[0] = sum * ((float)Nn / (float)NLOSS);
                g_done = 0;                   // reset for next graph replay
            }
        }
    }
}

// ---------------------------------------------------------------------------
extern "C" void kernel_launch(void* const* d_in, const int* in_sizes, int n_in,
                              void* d_out, int out_size)
{
    const float* emb   = (const float*)d_in[0];
    const float* aa    = (const float*)d_in[1];
    const float* fdiff = (const float*)d_in[2];
    const float* W1l   = (const float*)d_in[3];
    const float* b1l   = (const float*)d_in[4];
    const float* W2l   = (const float*)d_in[5];
    const float* b2l   = (const float*)d_in[6];
    const float* W1a   = (const float*)d_in[7];
    const float* b1a   = (const float*)d_in[8];
    const float* W2a   = (const float*)d_in[9];
    const float* b2a   = (const float*)d_in[10];
    const float* emw   = (const float*)d_in[11];
    const float* stw   = (const float*)d_in[12];
    const int*   pose  = (const int*)d_in[13];
    const int*   nege  = (const int*)d_in[14];
    const int*   pote  = (const int*)d_in[15];
    float* out = (float*)d_out;

    prep_kernel<<<384, 256>>>(W1l, W1a, W2l, W2a);

    dim3 mgrid(Nn / 64, 2);
    mlp_kernel<<<mgrid, 128>>>(emb, b1l, b2l, b1a, b2a);

    edge_kernel<<<EDGE_BLKS, 256>>>(aa, fdiff, pose, nege, pote, emw, stw, out);
}